// round 1
// baseline (speedup 1.0000x reference)
#include <cuda_runtime.h>
#include <cuda_fp16.h>
#include <cstdint>

// Problem constants
#define B_   4
#define T_   2048
#define D_   2048
#define H_   16
#define HD_  128
#define DFF_ 8192
#define R_   (B_*T_)      // 8192 rows

// ------------------------------------------------------------------
// Device scratch (module-static; allocation inside kernel_launch is banned)
// ------------------------------------------------------------------
__device__ __align__(256) __half g_h  [(size_t)R_*D_];       // LN1 output
__device__ __align__(256) __half g_h2 [(size_t)R_*D_];       // LN2 output
__device__ __align__(256) __half g_Wq [(size_t)H_*D_*HD_];
__device__ __align__(256) __half g_Wk [(size_t)H_*D_*HD_];
__device__ __align__(256) __half g_Wv [(size_t)H_*D_*HD_];
__device__ __align__(256) __half g_W1 [(size_t)D_*DFF_];
__device__ __align__(256) __half g_W2 [(size_t)DFF_*D_];
__device__ __align__(256) __half g_q  [(size_t)B_*H_*T_*HD_];
__device__ __align__(256) __half g_k  [(size_t)B_*H_*T_*HD_];
__device__ __align__(256) __half g_v  [(size_t)B_*H_*T_*HD_];
__device__ __align__(256) __half g_att[(size_t)R_*D_];       // attention out [B,T,D]
__device__ __align__(256) __half g_ff [(size_t)R_*DFF_];     // FFN1 output

// ------------------------------------------------------------------
// fp32 -> fp16 conversion
// ------------------------------------------------------------------
__global__ void f2h_kernel(const float* __restrict__ src, __half* __restrict__ dst, int n) {
    int i = blockIdx.x * blockDim.x + threadIdx.x;
    if (i < n) dst[i] = __float2half(src[i]);
}

// ------------------------------------------------------------------
// LayerNorm (block per row of D_=2048, 256 threads)
// ------------------------------------------------------------------
__global__ void __launch_bounds__(256) ln_kernel(
    const float* __restrict__ x, const float* __restrict__ g,
    const float* __restrict__ b, __half* __restrict__ out)
{
    int r = blockIdx.x;
    size_t off = (size_t)r * D_;
    float v[8], s = 0.f, s2 = 0.f;
#pragma unroll
    for (int j = 0; j < 8; j++) {
        float val = x[off + threadIdx.x + j*256];
        v[j] = val; s += val; s2 += val*val;
    }
    __shared__ float red[32];
#pragma unroll
    for (int o = 16; o; o >>= 1) { s += __shfl_xor_sync(~0u, s, o); s2 += __shfl_xor_sync(~0u, s2, o); }
    int wid = threadIdx.x >> 5;
    if ((threadIdx.x & 31) == 0) { red[wid] = s; red[8 + wid] = s2; }
    __syncthreads();
    if (threadIdx.x < 32) {
        float a  = (threadIdx.x < 8) ? red[threadIdx.x]   : 0.f;
        float c2 = (threadIdx.x < 8) ? red[8+threadIdx.x] : 0.f;
#pragma unroll
        for (int o = 4; o; o >>= 1) { a += __shfl_xor_sync(~0u, a, o); c2 += __shfl_xor_sync(~0u, c2, o); }
        if (threadIdx.x == 0) { red[16] = a; red[17] = c2; }
    }
    __syncthreads();
    float mu  = red[16] * (1.f / D_);
    float var = red[17] * (1.f / D_) - mu * mu;
    float rs  = rsqrtf(var + 1e-5f);
#pragma unroll
    for (int j = 0; j < 8; j++) {
        int c = threadIdx.x + j*256;
        out[off + c] = __float2half((v[j] - mu) * rs * g[c] + b[c]);
    }
}

// Fused: x1 = x + att ; write x1 to xout (fp32) ; h2 = LN(x1)
__global__ void __launch_bounds__(256) resid_ln_kernel(
    const float* __restrict__ x, const float* __restrict__ g,
    const float* __restrict__ b, float* __restrict__ xout,
    __half* __restrict__ h2)
{
    int r = blockIdx.x;
    size_t off = (size_t)r * D_;
    float v[8], s = 0.f, s2 = 0.f;
#pragma unroll
    for (int j = 0; j < 8; j++) {
        int c = threadIdx.x + j*256;
        float val = x[off + c] + __half2float(g_att[off + c]);
        xout[off + c] = val;
        v[j] = val; s += val; s2 += val*val;
    }
    __shared__ float red[32];
#pragma unroll
    for (int o = 16; o; o >>= 1) { s += __shfl_xor_sync(~0u, s, o); s2 += __shfl_xor_sync(~0u, s2, o); }
    int wid = threadIdx.x >> 5;
    if ((threadIdx.x & 31) == 0) { red[wid] = s; red[8 + wid] = s2; }
    __syncthreads();
    if (threadIdx.x < 32) {
        float a  = (threadIdx.x < 8) ? red[threadIdx.x]   : 0.f;
        float c2 = (threadIdx.x < 8) ? red[8+threadIdx.x] : 0.f;
#pragma unroll
        for (int o = 4; o; o >>= 1) { a += __shfl_xor_sync(~0u, a, o); c2 += __shfl_xor_sync(~0u, c2, o); }
        if (threadIdx.x == 0) { red[16] = a; red[17] = c2; }
    }
    __syncthreads();
    float mu  = red[16] * (1.f / D_);
    float var = red[17] * (1.f / D_) - mu * mu;
    float rs  = rsqrtf(var + 1e-5f);
#pragma unroll
    for (int j = 0; j < 8; j++) {
        int c = threadIdx.x + j*256;
        h2[off + c] = __float2half((v[j] - mu) * rs * g[c] + b[c]);
    }
}

// ------------------------------------------------------------------
// mma.sync m16n8k16 f16 (fp32 accum)
// ------------------------------------------------------------------
__device__ __forceinline__ void mma_16816(float* c, const uint32_t* a, uint32_t b0, uint32_t b1v) {
    asm volatile(
        "mma.sync.aligned.m16n8k16.row.col.f32.f16.f16.f32 "
        "{%0,%1,%2,%3}, {%4,%5,%6,%7}, {%8,%9}, {%0,%1,%2,%3};\n"
        : "+f"(c[0]), "+f"(c[1]), "+f"(c[2]), "+f"(c[3])
        : "r"(a[0]), "r"(a[1]), "r"(a[2]), "r"(a[3]), "r"(b0), "r"(b1v));
}

__device__ __forceinline__ uint32_t packh2(float a, float b) {
    __half2 h = __floats2half2_rn(a, b);
    return *reinterpret_cast<uint32_t*>(&h);
}

// ------------------------------------------------------------------
// Generic fp16 GEMM: C[M,N] = A[M,K] * B[K,N]
//   mode 0: QKV  (A=g_h, per-(which,head) W; out -> g_q/g_k/g_v [B,H,T,HD], +bias)
//   mode 1: FFN1 (A=g_h2, B=g_W1; out = relu(C+b1) -> g_ff fp16)
//   mode 2: FFN2 (A=g_ff, B=g_W2; xout[r,n] += C + b2)
// Tiles: BM=128, BN=128, BK=64; 256 threads (8 warps, 2x4), warp tile 64x32.
// ------------------------------------------------------------------
#define BM 128
#define BN 128
#define BK 64

__global__ void __launch_bounds__(256) gemm_kernel(
    int mode,
    const float* __restrict__ bq, const float* __restrict__ bk, const float* __restrict__ bv,
    const float* __restrict__ b1, const float* __restrict__ b2,
    float* __restrict__ xout)
{
    const __half* Aglob; const __half* Bmat; __half* outh = nullptr;
    const float* bias; int K, ldb; int head = 0;

    if (mode == 0) {
        Aglob = g_h; K = D_; ldb = HD_;
        int which = blockIdx.z >> 4; head = blockIdx.z & 15;
        Bmat = (which == 0 ? g_Wq : which == 1 ? g_Wk : g_Wv) + (size_t)head * (D_ * HD_);
        bias = (which == 0 ? bq : which == 1 ? bk : bv) + head * HD_;
        outh = (which == 0 ? g_q : which == 1 ? g_k : g_v);
    } else if (mode == 1) {
        Aglob = g_h2; Bmat = g_W1; K = D_; ldb = DFF_; bias = b1; outh = g_ff;
    } else {
        Aglob = g_ff; Bmat = g_W2; K = DFF_; ldb = D_; bias = b2;
    }

    const int m0 = blockIdx.x * BM;
    const int n0 = blockIdx.y * BN;

    __shared__ __half As[BM][BK + 8];   // [128][72]
    __shared__ __half Bs[BN][BK + 8];   // transposed: [n][k]

    const int wid  = threadIdx.x >> 5;
    const int lane = threadIdx.x & 31;
    const int wm   = wid & 1;           // 0..1
    const int wn   = wid >> 1;          // 0..3

    float acc[4][4][4];
#pragma unroll
    for (int i = 0; i < 4; i++)
#pragma unroll
        for (int j = 0; j < 4; j++)
#pragma unroll
            for (int q = 0; q < 4; q++) acc[i][j][q] = 0.f;

    for (int kt = 0; kt < K; kt += BK) {
        // Load A tile (128x64) and B tile (64x128, transposed into Bs)
#pragma unroll
        for (int c = 0; c < 4; c++) {
            int chunk = threadIdx.x + c * 256;
            int arow = chunk >> 3, acol = (chunk & 7) << 3;
            *(uint4*)&As[arow][acol] =
                *(const uint4*)(Aglob + (size_t)(m0 + arow) * K + kt + acol);
            int brow = chunk >> 4, bcol = (chunk & 15) << 3;
            uint4 bv4 = *(const uint4*)(Bmat + (size_t)(kt + brow) * ldb + n0 + bcol);
            const __half* hp = (const __half*)&bv4;
#pragma unroll
            for (int jj = 0; jj < 8; jj++) Bs[bcol + jj][brow] = hp[jj];
        }
        __syncthreads();

#pragma unroll
        for (int kk = 0; kk < 4; kk++) {
            uint32_t a[4][4];
#pragma unroll
            for (int mt = 0; mt < 4; mt++) {
                int r0 = wm * 64 + mt * 16 + (lane >> 2);
                int c0 = ((lane & 3) << 1) + kk * 16;
                a[mt][0] = *(const uint32_t*)&As[r0][c0];
                a[mt][1] = *(const uint32_t*)&As[r0 + 8][c0];
                a[mt][2] = *(const uint32_t*)&As[r0][c0 + 8];
                a[mt][3] = *(const uint32_t*)&As[r0 + 8][c0 + 8];
            }
#pragma unroll
            for (int nt = 0; nt < 4; nt++) {
                int n  = wn * 32 + nt * 8 + (lane >> 2);
                int kb = ((lane & 3) << 1) + kk * 16;
                uint32_t b0  = *(const uint32_t*)&Bs[n][kb];
                uint32_t b1v = *(const uint32_t*)&Bs[n][kb + 8];
#pragma unroll
                for (int mt = 0; mt < 4; mt++) mma_16816(acc[mt][nt], a[mt], b0, b1v);
            }
        }
        __syncthreads();
    }

    // Epilogue
#pragma unroll
    for (int mt = 0; mt < 4; mt++) {
#pragma unroll
        for (int nt = 0; nt < 4; nt++) {
            float* cc = acc[mt][nt];
            int row0 = m0 + wm * 64 + mt * 16 + (lane >> 2);
            int col  = n0 + wn * 32 + nt * 8 + ((lane & 3) << 1);
            float bb0 = bias[col], bb1 = bias[col + 1];
            if (mode == 0) {
#pragma unroll
                for (int rr = 0; rr < 2; rr++) {
                    int row = row0 + rr * 8;
                    int bb = row >> 11, t = row & (T_ - 1);
                    __half* dst = outh + (((size_t)(bb * H_ + head) * T_ + t) * HD_) + col;
                    *(__half2*)dst = __floats2half2_rn(cc[rr*2] + bb0, cc[rr*2+1] + bb1);
                }
            } else if (mode == 1) {
#pragma unroll
                for (int rr = 0; rr < 2; rr++) {
                    int row = row0 + rr * 8;
                    float v0 = fmaxf(cc[rr*2]   + bb0, 0.f);
                    float v1 = fmaxf(cc[rr*2+1] + bb1, 0.f);
                    *(__half2*)(outh + (size_t)row * DFF_ + col) = __floats2half2_rn(v0, v1);
                }
            } else {
#pragma unroll
                for (int rr = 0; rr < 2; rr++) {
                    int row = row0 + rr * 8;
                    float* d = xout + (size_t)row * D_ + col;
                    d[0] += cc[rr*2]   + bb0;
                    d[1] += cc[rr*2+1] + bb1;
                }
            }
        }
    }
}

// ------------------------------------------------------------------
// Flash attention: grid (T/64, B*H), 128 threads (4 warps x 16 q rows)
// ------------------------------------------------------------------
#define AQ 64
#define AK 64

__global__ void __launch_bounds__(128) attn_kernel() {
    const int bh = blockIdx.y;              // b*H + h
    const int b  = bh >> 4, h = bh & 15;
    const int t0 = blockIdx.x * AQ;

    const __half* qbase = g_q + (size_t)bh * T_ * HD_;
    const __half* kbase = g_k + (size_t)bh * T_ * HD_;
    const __half* vbase = g_v + (size_t)bh * T_ * HD_;

    __shared__ __half Ks[AK][HD_ + 8];      // [64][136]
    __shared__ __half Vs[HD_][AK + 8];      // transposed [e][s]: [128][72]

    const int wid  = threadIdx.x >> 5;
    const int lane = threadIdx.x & 31;
    const int qr   = wid * 16 + (lane >> 2);   // fragment base row within tile

    // Q fragments in registers (reused across all KV tiles)
    uint32_t qa[8][4];
    {
        const __half* qp = qbase + (size_t)t0 * HD_;
#pragma unroll
        for (int kk = 0; kk < 8; kk++) {
            int c = ((lane & 3) << 1) + kk * 16;
            qa[kk][0] = *(const uint32_t*)(qp + (size_t)qr       * HD_ + c);
            qa[kk][1] = *(const uint32_t*)(qp + (size_t)(qr + 8) * HD_ + c);
            qa[kk][2] = *(const uint32_t*)(qp + (size_t)qr       * HD_ + c + 8);
            qa[kk][3] = *(const uint32_t*)(qp + (size_t)(qr + 8) * HD_ + c + 8);
        }
    }

    float m_run[2] = {-1e30f, -1e30f};
    float l_run[2] = {0.f, 0.f};
    float o[16][4];
#pragma unroll
    for (int i = 0; i < 16; i++)
#pragma unroll
        for (int q = 0; q < 4; q++) o[i][q] = 0.f;

    const float scale = 0.08838834764831845f;  // 1/sqrt(128)
    const int jmax = t0 / AK;

    for (int j = 0; j <= jmax; j++) {
        const int s0 = j * AK;
        __syncthreads();
        for (int c = threadIdx.x; c < (AK * HD_ / 8); c += 128) {
            int row = c >> 4, col = (c & 15) << 3;
            *(uint4*)&Ks[row][col] =
                *(const uint4*)(kbase + (size_t)(s0 + row) * HD_ + col);
            uint4 vv = *(const uint4*)(vbase + (size_t)(s0 + row) * HD_ + col);
            const __half* hp = (const __half*)&vv;
#pragma unroll
            for (int jj = 0; jj < 8; jj++) Vs[col + jj][row] = hp[jj];
        }
        __syncthreads();

        // S = Q K^T  (16x64 per warp)
        float sacc[8][4];
#pragma unroll
        for (int nt = 0; nt < 8; nt++)
#pragma unroll
            for (int q = 0; q < 4; q++) sacc[nt][q] = 0.f;

#pragma unroll
        for (int kk = 0; kk < 8; kk++) {
#pragma unroll
            for (int nt = 0; nt < 8; nt++) {
                int n  = nt * 8 + (lane >> 2);
                int kb = ((lane & 3) << 1) + kk * 16;
                uint32_t b0  = *(const uint32_t*)&Ks[n][kb];
                uint32_t b1v = *(const uint32_t*)&Ks[n][kb + 8];
                mma_16816(sacc[nt], qa[kk], b0, b1v);
            }
        }

        // scale + causal mask + per-row tile max
        const int tg0 = t0 + wid * 16 + (lane >> 2);
        float mtile[2] = {-1e30f, -1e30f};
#pragma unroll
        for (int nt = 0; nt < 8; nt++) {
            int sg = s0 + nt * 8 + ((lane & 3) << 1);
#pragma unroll
            for (int q = 0; q < 4; q++) {
                int rsel = q >> 1;
                int scol = sg + (q & 1);
                int tg   = tg0 + (rsel ? 8 : 0);
                float vv = sacc[nt][q] * scale;
                if (scol > tg) vv = -1e30f;
                sacc[nt][q] = vv;
                mtile[rsel] = fmaxf(mtile[rsel], vv);
            }
        }
#pragma unroll
        for (int o2 = 1; o2 < 4; o2 <<= 1) {
            mtile[0] = fmaxf(mtile[0], __shfl_xor_sync(~0u, mtile[0], o2));
            mtile[1] = fmaxf(mtile[1], __shfl_xor_sync(~0u, mtile[1], o2));
        }
        float mnew[2] = {fmaxf(m_run[0], mtile[0]), fmaxf(m_run[1], mtile[1])};
        float corr[2] = {__expf(m_run[0] - mnew[0]), __expf(m_run[1] - mnew[1])};

        // P = exp(S - m), pack to fp16 A-fragments
        float pl[2] = {0.f, 0.f};
        uint32_t pa[4][4];
#pragma unroll
        for (int nt = 0; nt < 8; nt++) {
            float p0 = __expf(sacc[nt][0] - mnew[0]);
            float p1 = __expf(sacc[nt][1] - mnew[0]);
            float p2 = __expf(sacc[nt][2] - mnew[1]);
            float p3 = __expf(sacc[nt][3] - mnew[1]);
            pl[0] += p0 + p1; pl[1] += p2 + p3;
            int kk2 = nt >> 1, hi = nt & 1;
            pa[kk2][2*hi]     = packh2(p0, p1);
            pa[kk2][2*hi + 1] = packh2(p2, p3);
        }
#pragma unroll
        for (int o2 = 1; o2 < 4; o2 <<= 1) {
            pl[0] += __shfl_xor_sync(~0u, pl[0], o2);
            pl[1] += __shfl_xor_sync(~0u, pl[1], o2);
        }
        l_run[0] = l_run[0] * corr[0] + pl[0];
        l_run[1] = l_run[1] * corr[1] + pl[1];
        m_run[0] = mnew[0]; m_run[1] = mnew[1];

        // rescale O, then O += P @ V
#pragma unroll
        for (int nt = 0; nt < 16; nt++) {
            o[nt][0] *= corr[0]; o[nt][1] *= corr[0];
            o[nt][2] *= corr[1]; o[nt][3] *= corr[1];
        }
#pragma unroll
        for (int kk2 = 0; kk2 < 4; kk2++) {
#pragma unroll
            for (int nt = 0; nt < 16; nt++) {
                int e  = nt * 8 + (lane >> 2);
                int kb = ((lane & 3) << 1) + kk2 * 16;
                uint32_t b0  = *(const uint32_t*)&Vs[e][kb];
                uint32_t b1v = *(const uint32_t*)&Vs[e][kb + 8];
                mma_16816(o[nt], pa[kk2], b0, b1v);
            }
        }
    }

    // write normalized O to g_att[b, t, h*HD + e]
    float inv0 = 1.f / l_run[0], inv1 = 1.f / l_run[1];
    const int tg = t0 + wid * 16 + (lane >> 2);
    size_t base0 = ((size_t)b * T_ + tg)     * D_ + h * HD_;
    size_t base1 = ((size_t)b * T_ + tg + 8) * D_ + h * HD_;
#pragma unroll
    for (int nt = 0; nt < 16; nt++) {
        int e = nt * 8 + ((lane & 3) << 1);
        *(__half2*)(g_att + base0 + e) = __floats2half2_rn(o[nt][0] * inv0, o[nt][1] * inv0);
        *(__half2*)(g_att + base1 + e) = __floats2half2_rn(o[nt][2] * inv1, o[nt][3] * inv1);
    }
}

// ------------------------------------------------------------------
// Launch
// ------------------------------------------------------------------
extern "C" void kernel_launch(void* const* d_in, const int* in_sizes, int n_in,
                              void* d_out, int out_size) {
    const float* x   = (const float*)d_in[0];
    const float* Wq  = (const float*)d_in[1];
    const float* bq  = (const float*)d_in[2];
    const float* Wk  = (const float*)d_in[3];
    const float* bk  = (const float*)d_in[4];
    const float* Wv  = (const float*)d_in[5];
    const float* bv  = (const float*)d_in[6];
    const float* W1  = (const float*)d_in[7];
    const float* b1  = (const float*)d_in[8];
    const float* W2  = (const float*)d_in[9];
    const float* b2  = (const float*)d_in[10];
    const float* g1  = (const float*)d_in[11];
    const float* be1 = (const float*)d_in[12];
    const float* g2  = (const float*)d_in[13];
    const float* be2 = (const float*)d_in[14];
    float* out = (float*)d_out;

    __half *pWq, *pWk, *pWv, *pW1, *pW2, *pH, *pH2;
    cudaGetSymbolAddress((void**)&pWq, g_Wq);
    cudaGetSymbolAddress((void**)&pWk, g_Wk);
    cudaGetSymbolAddress((void**)&pWv, g_Wv);
    cudaGetSymbolAddress((void**)&pW1, g_W1);
    cudaGetSymbolAddress((void**)&pW2, g_W2);
    cudaGetSymbolAddress((void**)&pH,  g_h);
    cudaGetSymbolAddress((void**)&pH2, g_h2);

    const int nW  = H_ * D_ * HD_;   // 4,194,304
    const int nW1 = D_ * DFF_;       // 16,777,216

    f2h_kernel<<<nW  / 256, 256>>>(Wq, pWq, nW);
    f2h_kernel<<<nW  / 256, 256>>>(Wk, pWk, nW);
    f2h_kernel<<<nW  / 256, 256>>>(Wv, pWv, nW);
    f2h_kernel<<<nW1 / 256, 256>>>(W1, pW1, nW1);
    f2h_kernel<<<nW1 / 256, 256>>>(W2, pW2, nW1);

    // LN1
    ln_kernel<<<R_, 256>>>(x, g1, be1, pH);

    // QKV: grid (M/128, 1, 3*16)
    gemm_kernel<<<dim3(R_ / BM, 1, 48), 256>>>(0, bq, bk, bv, b1, b2, out);

    // attention
    attn_kernel<<<dim3(T_ / AQ, B_ * H_), 128>>>();

    // residual + LN2 (writes x1 into d_out)
    resid_ln_kernel<<<R_, 256>>>(x, g2, be2, out, pH2);

    // FFN1: [8192,2048]x[2048,8192] relu -> g_ff
    gemm_kernel<<<dim3(R_ / BM, DFF_ / BN, 1), 256>>>(1, bq, bk, bv, b1, b2, out);

    // FFN2: [8192,8192]x[8192,2048], d_out += C + b2
    gemm_kernel<<<dim3(R_ / BM, D_ / BN, 1), 256>>>(2, bq, bk, bv, b1, b2, out);
}

// round 2
// speedup vs baseline: 4.2553x; 4.2553x over previous
#include <cuda_runtime.h>
#include <cuda_fp16.h>
#include <cstdint>

// Problem constants
#define B_   4
#define T_   2048
#define D_   2048
#define H_   16
#define HD_  128
#define DFF_ 8192
#define R_   (B_*T_)      // 8192 rows

// ------------------------------------------------------------------
// Device scratch
// ------------------------------------------------------------------
__device__ __align__(256) __half g_h  [(size_t)R_*D_];
__device__ __align__(256) __half g_h2 [(size_t)R_*D_];
__device__ __align__(256) __half g_Wq [(size_t)H_*D_*HD_];
__device__ __align__(256) __half g_Wk [(size_t)H_*D_*HD_];
__device__ __align__(256) __half g_Wv [(size_t)H_*D_*HD_];
__device__ __align__(256) __half g_W1 [(size_t)D_*DFF_];
__device__ __align__(256) __half g_W2 [(size_t)DFF_*D_];
__device__ __align__(256) __half g_q  [(size_t)B_*H_*T_*HD_];
__device__ __align__(256) __half g_k  [(size_t)B_*H_*T_*HD_];
__device__ __align__(256) __half g_v  [(size_t)B_*H_*T_*HD_];
__device__ __align__(256) __half g_att[(size_t)R_*D_];
__device__ __align__(256) __half g_ff [(size_t)R_*DFF_];

// ------------------------------------------------------------------
// Helpers
// ------------------------------------------------------------------
__device__ __forceinline__ uint32_t smem_u32(const void* p) {
    return (uint32_t)__cvta_generic_to_shared(p);
}
__device__ __forceinline__ void cp16(uint32_t dst, const void* src) {
    asm volatile("cp.async.cg.shared.global [%0], [%1], 16;" :: "r"(dst), "l"(src));
}
#define CP_COMMIT() asm volatile("cp.async.commit_group;")
#define CP_WAIT0()  asm volatile("cp.async.wait_group 0;")

__device__ __forceinline__ void ldsm_x4(uint32_t& r0, uint32_t& r1, uint32_t& r2, uint32_t& r3, uint32_t a) {
    asm volatile("ldmatrix.sync.aligned.m8n8.x4.shared.b16 {%0,%1,%2,%3}, [%4];"
                 : "=r"(r0), "=r"(r1), "=r"(r2), "=r"(r3) : "r"(a));
}
__device__ __forceinline__ void ldsm_x4_t(uint32_t& r0, uint32_t& r1, uint32_t& r2, uint32_t& r3, uint32_t a) {
    asm volatile("ldmatrix.sync.aligned.m8n8.x4.trans.shared.b16 {%0,%1,%2,%3}, [%4];"
                 : "=r"(r0), "=r"(r1), "=r"(r2), "=r"(r3) : "r"(a));
}
__device__ __forceinline__ void mma_16816(float* c, const uint32_t* a, uint32_t b0, uint32_t b1v) {
    asm volatile(
        "mma.sync.aligned.m16n8k16.row.col.f32.f16.f16.f32 "
        "{%0,%1,%2,%3}, {%4,%5,%6,%7}, {%8,%9}, {%0,%1,%2,%3};\n"
        : "+f"(c[0]), "+f"(c[1]), "+f"(c[2]), "+f"(c[3])
        : "r"(a[0]), "r"(a[1]), "r"(a[2]), "r"(a[3]), "r"(b0), "r"(b1v));
}
__device__ __forceinline__ uint32_t packh2(float a, float b) {
    __half2 h = __floats2half2_rn(a, b);
    return *reinterpret_cast<uint32_t*>(&h);
}

// ------------------------------------------------------------------
// fp32 -> fp16 conversion, 8 elems/thread
// ------------------------------------------------------------------
__global__ void f2h_kernel(const float4* __restrict__ src, uint4* __restrict__ dst, int n8) {
    int i = blockIdx.x * blockDim.x + threadIdx.x;
    if (i >= n8) return;
    float4 a = src[2*i], b = src[2*i + 1];
    __half2 h0 = __floats2half2_rn(a.x, a.y);
    __half2 h1 = __floats2half2_rn(a.z, a.w);
    __half2 h2 = __floats2half2_rn(b.x, b.y);
    __half2 h3 = __floats2half2_rn(b.z, b.w);
    uint4 o;
    o.x = *(uint32_t*)&h0; o.y = *(uint32_t*)&h1;
    o.z = *(uint32_t*)&h2; o.w = *(uint32_t*)&h3;
    dst[i] = o;
}

// ------------------------------------------------------------------
// LayerNorm (block per row of D_=2048, 256 threads)
// ------------------------------------------------------------------
__global__ void __launch_bounds__(256) ln_kernel(
    const float* __restrict__ x, const float* __restrict__ g,
    const float* __restrict__ b, __half* __restrict__ out)
{
    int r = blockIdx.x;
    size_t off = (size_t)r * D_;
    float v[8], s = 0.f, s2 = 0.f;
#pragma unroll
    for (int j = 0; j < 8; j++) {
        float val = x[off + threadIdx.x + j*256];
        v[j] = val; s += val; s2 += val*val;
    }
    __shared__ float red[32];
#pragma unroll
    for (int o = 16; o; o >>= 1) { s += __shfl_xor_sync(~0u, s, o); s2 += __shfl_xor_sync(~0u, s2, o); }
    int wid = threadIdx.x >> 5;
    if ((threadIdx.x & 31) == 0) { red[wid] = s; red[8 + wid] = s2; }
    __syncthreads();
    if (threadIdx.x < 32) {
        float a  = (threadIdx.x < 8) ? red[threadIdx.x]   : 0.f;
        float c2 = (threadIdx.x < 8) ? red[8+threadIdx.x] : 0.f;
#pragma unroll
        for (int o = 4; o; o >>= 1) { a += __shfl_xor_sync(~0u, a, o); c2 += __shfl_xor_sync(~0u, c2, o); }
        if (threadIdx.x == 0) { red[16] = a; red[17] = c2; }
    }
    __syncthreads();
    float mu  = red[16] * (1.f / D_);
    float var = red[17] * (1.f / D_) - mu * mu;
    float rs  = rsqrtf(var + 1e-5f);
#pragma unroll
    for (int j = 0; j < 8; j++) {
        int c = threadIdx.x + j*256;
        out[off + c] = __float2half((v[j] - mu) * rs * g[c] + b[c]);
    }
}

// Fused: x1 = x + att ; write x1 to xout (fp32) ; h2 = LN(x1)
__global__ void __launch_bounds__(256) resid_ln_kernel(
    const float* __restrict__ x, const float* __restrict__ g,
    const float* __restrict__ b, float* __restrict__ xout,
    __half* __restrict__ h2)
{
    int r = blockIdx.x;
    size_t off = (size_t)r * D_;
    float v[8], s = 0.f, s2 = 0.f;
#pragma unroll
    for (int j = 0; j < 8; j++) {
        int c = threadIdx.x + j*256;
        float val = x[off + c] + __half2float(g_att[off + c]);
        xout[off + c] = val;
        v[j] = val; s += val; s2 += val*val;
    }
    __shared__ float red[32];
#pragma unroll
    for (int o = 16; o; o >>= 1) { s += __shfl_xor_sync(~0u, s, o); s2 += __shfl_xor_sync(~0u, s2, o); }
    int wid = threadIdx.x >> 5;
    if ((threadIdx.x & 31) == 0) { red[wid] = s; red[8 + wid] = s2; }
    __syncthreads();
    if (threadIdx.x < 32) {
        float a  = (threadIdx.x < 8) ? red[threadIdx.x]   : 0.f;
        float c2 = (threadIdx.x < 8) ? red[8+threadIdx.x] : 0.f;
#pragma unroll
        for (int o = 4; o; o >>= 1) { a += __shfl_xor_sync(~0u, a, o); c2 += __shfl_xor_sync(~0u, c2, o); }
        if (threadIdx.x == 0) { red[16] = a; red[17] = c2; }
    }
    __syncthreads();
    float mu  = red[16] * (1.f / D_);
    float var = red[17] * (1.f / D_) - mu * mu;
    float rs  = rsqrtf(var + 1e-5f);
#pragma unroll
    for (int j = 0; j < 8; j++) {
        int c = threadIdx.x + j*256;
        h2[off + c] = __float2half((v[j] - mu) * rs * g[c] + b[c]);
    }
}

// ------------------------------------------------------------------
// GEMM: C[M,N] = A[M,K]*B[K,N], cp.async double-buffered, ldmatrix,
// XOR-swizzled smem. BM=128, BN=128, BK=64, 256 threads (2x4 warps).
//   mode 0: QKV   mode 1: FFN1 (relu)   mode 2: FFN2 (xout += C + b2)
// ------------------------------------------------------------------
#define BM 128
#define BN 128
#define BK 64

__global__ void __launch_bounds__(256, 2) gemm_kernel(
    int mode,
    const float* __restrict__ bq, const float* __restrict__ bk, const float* __restrict__ bv,
    const float* __restrict__ b1, const float* __restrict__ b2,
    float* __restrict__ xout)
{
    const __half* Aglob; const __half* Bmat; __half* outh = nullptr;
    const float* bias; int K, ldb; int head = 0;

    if (mode == 0) {
        Aglob = g_h; K = D_; ldb = HD_;
        int which = blockIdx.z >> 4; head = blockIdx.z & 15;
        Bmat = (which == 0 ? g_Wq : which == 1 ? g_Wk : g_Wv) + (size_t)head * (D_ * HD_);
        bias = (which == 0 ? bq : which == 1 ? bk : bv) + head * HD_;
        outh = (which == 0 ? g_q : which == 1 ? g_k : g_v);
    } else if (mode == 1) {
        Aglob = g_h2; Bmat = g_W1; K = D_; ldb = DFF_; bias = b1; outh = g_ff;
    } else {
        Aglob = g_ff; Bmat = g_W2; K = DFF_; ldb = D_; bias = b2;
    }

    const int m0 = blockIdx.x * BM;
    const int n0 = blockIdx.y * BN;

    extern __shared__ __half dsm[];
    __half* As = dsm;                       // [2][BM][BK]
    __half* Bs = dsm + 2 * BM * BK;         // [2][BK][BN]

    const int wid  = threadIdx.x >> 5;
    const int lane = threadIdx.x & 31;
    const int wm   = wid & 1;               // 0..1
    const int wn   = wid >> 1;              // 0..3

    float acc[4][4][4];
#pragma unroll
    for (int i = 0; i < 4; i++)
#pragma unroll
        for (int j = 0; j < 4; j++)
#pragma unroll
            for (int q = 0; q < 4; q++) acc[i][j][q] = 0.f;

    const int nkt = K / BK;

    // prefetch tile kt into buffer buf
    auto prefetch = [&](int kt, int buf) {
#pragma unroll
        for (int c = 0; c < 4; c++) {
            int idx  = threadIdx.x + c * 256;
            int arow = idx >> 3, ach = idx & 7;
            const __half* asrc = Aglob + (size_t)(m0 + arow) * K + kt * BK + ach * 8;
            cp16(smem_u32(As + ((buf * BM + arow) * BK) + ((ach ^ (arow & 7)) << 3)), asrc);
            int brow = idx >> 4, bch = idx & 15;
            const __half* bsrc = Bmat + (size_t)(kt * BK + brow) * ldb + n0 + bch * 8;
            cp16(smem_u32(Bs + ((buf * BK + brow) * BN) + ((bch ^ (brow & 7)) << 3)), bsrc);
        }
    };

    prefetch(0, 0);
    CP_COMMIT();

    for (int kt = 0; kt < nkt; kt++) {
        CP_WAIT0();
        __syncthreads();
        int cur = kt & 1;
        if (kt + 1 < nkt) { prefetch(kt + 1, cur ^ 1); CP_COMMIT(); }

        const __half* Ab = As + (size_t)cur * BM * BK;
        const __half* Bb = Bs + (size_t)cur * BK * BN;

#pragma unroll
        for (int kk = 0; kk < 4; kk++) {
            // A fragments: 4 m-tiles
            uint32_t a[4][4];
#pragma unroll
            for (int mt = 0; mt < 4; mt++) {
                int row = wm * 64 + mt * 16 + (lane & 15);
                int ch  = 2 * kk + (lane >> 4);
                uint32_t addr = smem_u32(Ab + row * BK + (((ch) ^ (row & 7)) << 3));
                ldsm_x4(a[mt][0], a[mt][1], a[mt][2], a[mt][3], addr);
            }
            // B fragments: 4 n-tiles via 2 trans-x4
            uint32_t bf[4][2];
#pragma unroll
            for (int ntp = 0; ntp < 2; ntp++) {
                int n0w = wn * 32 + ntp * 16;
                int row = kk * 16 + ((lane >> 3) & 1) * 8 + (lane & 7);
                int ch  = (n0w >> 3) + (lane >> 4);
                uint32_t addr = smem_u32(Bb + row * BN + ((((ch & 7) ^ (row & 7)) | (ch & 8)) << 3));
                ldsm_x4_t(bf[2*ntp][0], bf[2*ntp][1], bf[2*ntp+1][0], bf[2*ntp+1][1], addr);
            }
#pragma unroll
            for (int nt = 0; nt < 4; nt++)
#pragma unroll
                for (int mt = 0; mt < 4; mt++)
                    mma_16816(acc[mt][nt], a[mt], bf[nt][0], bf[nt][1]);
        }
        __syncthreads();
    }

    // Epilogue
#pragma unroll
    for (int mt = 0; mt < 4; mt++) {
#pragma unroll
        for (int nt = 0; nt < 4; nt++) {
            float* cc = acc[mt][nt];
            int row0 = m0 + wm * 64 + mt * 16 + (lane >> 2);
            int col  = n0 + wn * 32 + nt * 8 + ((lane & 3) << 1);
            float bb0 = bias[col], bb1 = bias[col + 1];
            if (mode == 0) {
#pragma unroll
                for (int rr = 0; rr < 2; rr++) {
                    int row = row0 + rr * 8;
                    int bb = row >> 11, t = row & (T_ - 1);
                    __half* dst = outh + (((size_t)(bb * H_ + head) * T_ + t) * HD_) + col;
                    *(__half2*)dst = __floats2half2_rn(cc[rr*2] + bb0, cc[rr*2+1] + bb1);
                }
            } else if (mode == 1) {
#pragma unroll
                for (int rr = 0; rr < 2; rr++) {
                    int row = row0 + rr * 8;
                    float v0 = fmaxf(cc[rr*2]   + bb0, 0.f);
                    float v1 = fmaxf(cc[rr*2+1] + bb1, 0.f);
                    *(__half2*)(outh + (size_t)row * DFF_ + col) = __floats2half2_rn(v0, v1);
                }
            } else {
#pragma unroll
                for (int rr = 0; rr < 2; rr++) {
                    int row = row0 + rr * 8;
                    float* d = xout + (size_t)row * D_ + col;
                    d[0] += cc[rr*2]   + bb0;
                    d[1] += cc[rr*2+1] + bb1;
                }
            }
        }
    }
}

// ------------------------------------------------------------------
// Flash attention: grid (T/64, B*H), 128 threads (4 warps x 16 q rows)
// K,V in smem row-major [s][e] with XOR swizzle; fragments via ldmatrix.
// ------------------------------------------------------------------
#define AQ 64
#define AK 64

__global__ void __launch_bounds__(128) attn_kernel() {
    const int bh = blockIdx.y;
    const int b  = bh >> 4, h = bh & 15;
    const int t0 = blockIdx.x * AQ;

    const __half* qbase = g_q + (size_t)bh * T_ * HD_;
    const __half* kbase = g_k + (size_t)bh * T_ * HD_;
    const __half* vbase = g_v + (size_t)bh * T_ * HD_;

    __shared__ __half Ks[AK][HD_];   // swizzled: 16 chunks/row, ch^ (s&7) on low 3 bits
    __shared__ __half Vs[AK][HD_];

    const int wid  = threadIdx.x >> 5;
    const int lane = threadIdx.x & 31;
    const int qr   = wid * 16 + (lane >> 2);

    // Q fragments in registers
    uint32_t qa[8][4];
    {
        const __half* qp = qbase + (size_t)t0 * HD_;
#pragma unroll
        for (int kk = 0; kk < 8; kk++) {
            int c = ((lane & 3) << 1) + kk * 16;
            qa[kk][0] = *(const uint32_t*)(qp + (size_t)qr       * HD_ + c);
            qa[kk][1] = *(const uint32_t*)(qp + (size_t)(qr + 8) * HD_ + c);
            qa[kk][2] = *(const uint32_t*)(qp + (size_t)qr       * HD_ + c + 8);
            qa[kk][3] = *(const uint32_t*)(qp + (size_t)(qr + 8) * HD_ + c + 8);
        }
    }

    float m_run[2] = {-1e30f, -1e30f};
    float l_run[2] = {0.f, 0.f};
    float o[16][4];
#pragma unroll
    for (int i = 0; i < 16; i++)
#pragma unroll
        for (int q = 0; q < 4; q++) o[i][q] = 0.f;

    const float scale = 0.08838834764831845f;
    const int jmax = t0 / AK;

    for (int j = 0; j <= jmax; j++) {
        const int s0 = j * AK;
        __syncthreads();
        for (int idx = threadIdx.x; idx < 1024; idx += 128) {
            int row = idx >> 4, ch = idx & 15;
            int sch = ((ch & 7) ^ (row & 7)) | (ch & 8);
            const __half* ksrc = kbase + (size_t)(s0 + row) * HD_ + ch * 8;
            const __half* vsrc = vbase + (size_t)(s0 + row) * HD_ + ch * 8;
            cp16(smem_u32(&Ks[row][sch << 3]), ksrc);
            cp16(smem_u32(&Vs[row][sch << 3]), vsrc);
        }
        CP_COMMIT();
        CP_WAIT0();
        __syncthreads();

        // S = Q K^T
        float sacc[8][4];
#pragma unroll
        for (int nt = 0; nt < 8; nt++)
#pragma unroll
            for (int q = 0; q < 4; q++) sacc[nt][q] = 0.f;

#pragma unroll
        for (int kk = 0; kk < 8; kk++) {
#pragma unroll
            for (int ntp = 0; ntp < 4; ntp++) {
                int row = ntp * 16 + ((lane >> 4) << 3) + (lane & 7);  // s-row
                int ch  = 2 * kk + ((lane >> 3) & 1);                  // e-chunk
                uint32_t addr = smem_u32(&Ks[row][(((ch & 7) ^ (row & 7)) | (ch & 8)) << 3]);
                uint32_t r0, r1, r2, r3;
                ldsm_x4(r0, r1, r2, r3, addr);
                mma_16816(sacc[2*ntp],   qa[kk], r0, r1);
                mma_16816(sacc[2*ntp+1], qa[kk], r2, r3);
            }
        }

        // scale + causal mask + tile max
        const int tg0 = t0 + wid * 16 + (lane >> 2);
        float mtile[2] = {-1e30f, -1e30f};
#pragma unroll
        for (int nt = 0; nt < 8; nt++) {
            int sg = s0 + nt * 8 + ((lane & 3) << 1);
#pragma unroll
            for (int q = 0; q < 4; q++) {
                int rsel = q >> 1;
                int scol = sg + (q & 1);
                int tg   = tg0 + (rsel ? 8 : 0);
                float vv = sacc[nt][q] * scale;
                if (scol > tg) vv = -1e30f;
                sacc[nt][q] = vv;
                mtile[rsel] = fmaxf(mtile[rsel], vv);
            }
        }
#pragma unroll
        for (int o2 = 1; o2 < 4; o2 <<= 1) {
            mtile[0] = fmaxf(mtile[0], __shfl_xor_sync(~0u, mtile[0], o2));
            mtile[1] = fmaxf(mtile[1], __shfl_xor_sync(~0u, mtile[1], o2));
        }
        float mnew[2] = {fmaxf(m_run[0], mtile[0]), fmaxf(m_run[1], mtile[1])};
        float corr[2] = {__expf(m_run[0] - mnew[0]), __expf(m_run[1] - mnew[1])};

        // P = exp(S - m)
        float pl[2] = {0.f, 0.f};
        uint32_t pa[4][4];
#pragma unroll
        for (int nt = 0; nt < 8; nt++) {
            float p0 = __expf(sacc[nt][0] - mnew[0]);
            float p1 = __expf(sacc[nt][1] - mnew[0]);
            float p2 = __expf(sacc[nt][2] - mnew[1]);
            float p3 = __expf(sacc[nt][3] - mnew[1]);
            pl[0] += p0 + p1; pl[1] += p2 + p3;
            int kk2 = nt >> 1, hi = nt & 1;
            pa[kk2][2*hi]     = packh2(p0, p1);
            pa[kk2][2*hi + 1] = packh2(p2, p3);
        }
#pragma unroll
        for (int o2 = 1; o2 < 4; o2 <<= 1) {
            pl[0] += __shfl_xor_sync(~0u, pl[0], o2);
            pl[1] += __shfl_xor_sync(~0u, pl[1], o2);
        }
        l_run[0] = l_run[0] * corr[0] + pl[0];
        l_run[1] = l_run[1] * corr[1] + pl[1];
        m_run[0] = mnew[0]; m_run[1] = mnew[1];

        // rescale O, then O += P @ V
#pragma unroll
        for (int nt = 0; nt < 16; nt++) {
            o[nt][0] *= corr[0]; o[nt][1] *= corr[0];
            o[nt][2] *= corr[1]; o[nt][3] *= corr[1];
        }
#pragma unroll
        for (int kk2 = 0; kk2 < 4; kk2++) {
#pragma unroll
            for (int etp = 0; etp < 8; etp++) {
                int row = kk2 * 16 + ((lane >> 3) & 1) * 8 + (lane & 7);  // s-row
                int ch  = etp * 2 + (lane >> 4);                          // e-chunk
                uint32_t addr = smem_u32(&Vs[row][(((ch & 7) ^ (row & 7)) | (ch & 8)) << 3]);
                uint32_t r0, r1, r2, r3;
                ldsm_x4_t(r0, r1, r2, r3, addr);
                mma_16816(o[2*etp],   pa[kk2], r0, r1);
                mma_16816(o[2*etp+1], pa[kk2], r2, r3);
            }
        }
    }

    // write normalized O
    float inv0 = 1.f / l_run[0], inv1 = 1.f / l_run[1];
    const int tg = t0 + wid * 16 + (lane >> 2);
    size_t base0 = ((size_t)b * T_ + tg)     * D_ + h * HD_;
    size_t base1 = ((size_t)b * T_ + tg + 8) * D_ + h * HD_;
#pragma unroll
    for (int nt = 0; nt < 16; nt++) {
        int e = nt * 8 + ((lane & 3) << 1);
        *(__half2*)(g_att + base0 + e) = __floats2half2_rn(o[nt][0] * inv0, o[nt][1] * inv0);
        *(__half2*)(g_att + base1 + e) = __floats2half2_rn(o[nt][2] * inv1, o[nt][3] * inv1);
    }
}

// ------------------------------------------------------------------
// Launch
// ------------------------------------------------------------------
extern "C" void kernel_launch(void* const* d_in, const int* in_sizes, int n_in,
                              void* d_out, int out_size) {
    const float* x   = (const float*)d_in[0];
    const float* Wq  = (const float*)d_in[1];
    const float* bq  = (const float*)d_in[2];
    const float* Wk  = (const float*)d_in[3];
    const float* bk  = (const float*)d_in[4];
    const float* Wv  = (const float*)d_in[5];
    const float* bv  = (const float*)d_in[6];
    const float* W1  = (const float*)d_in[7];
    const float* b1  = (const float*)d_in[8];
    const float* W2  = (const float*)d_in[9];
    const float* b2  = (const float*)d_in[10];
    const float* g1  = (const float*)d_in[11];
    const float* be1 = (const float*)d_in[12];
    const float* g2  = (const float*)d_in[13];
    const float* be2 = (const float*)d_in[14];
    float* out = (float*)d_out;

    __half *pWq, *pWk, *pWv, *pW1, *pW2, *pH, *pH2;
    cudaGetSymbolAddress((void**)&pWq, g_Wq);
    cudaGetSymbolAddress((void**)&pWk, g_Wk);
    cudaGetSymbolAddress((void**)&pWv, g_Wv);
    cudaGetSymbolAddress((void**)&pW1, g_W1);
    cudaGetSymbolAddress((void**)&pW2, g_W2);
    cudaGetSymbolAddress((void**)&pH,  g_h);
    cudaGetSymbolAddress((void**)&pH2, g_h2);

    const int nW  = H_ * D_ * HD_;   // 4,194,304
    const int nW1 = D_ * DFF_;       // 16,777,216

    f2h_kernel<<<(nW/8)  / 256, 256>>>((const float4*)Wq, (uint4*)pWq, nW/8);
    f2h_kernel<<<(nW/8)  / 256, 256>>>((const float4*)Wk, (uint4*)pWk, nW/8);
    f2h_kernel<<<(nW/8)  / 256, 256>>>((const float4*)Wv, (uint4*)pWv, nW/8);
    f2h_kernel<<<(nW1/8) / 256, 256>>>((const float4*)W1, (uint4*)pW1, nW1/8);
    f2h_kernel<<<(nW1/8) / 256, 256>>>((const float4*)W2, (uint4*)pW2, nW1/8);

    ln_kernel<<<R_, 256>>>(x, g1, be1, pH);

    const int GEMM_SMEM = 2 * (BM * BK + BK * BN) * (int)sizeof(__half);  // 65536
    static bool attr_set = false;
    if (!attr_set) {
        cudaFuncSetAttribute(gemm_kernel, cudaFuncAttributeMaxDynamicSharedMemorySize, GEMM_SMEM);
        attr_set = true;
    }

    gemm_kernel<<<dim3(R_ / BM, 1, 48), 256, GEMM_SMEM>>>(0, bq, bk, bv, b1, b2, out);

    attn_kernel<<<dim3(T_ / AQ, B_ * H_), 128>>>();

    resid_ln_kernel<<<R_, 256>>>(x, g2, be2, out, pH2);

    gemm_kernel<<<dim3(R_ / BM, DFF_ / BN, 1), 256, GEMM_SMEM>>>(1, bq, bk, bv, b1, b2, out);

    gemm_kernel<<<dim3(R_ / BM, D_ / BN, 1), 256, GEMM_SMEM>>>(2, bq, bk, bv, b1, b2, out);
}